// round 16
// baseline (speedup 1.0000x reference)
#include <cuda_runtime.h>
#include <cuda_fp16.h>
#include <cstdint>

#define SCALE 0.05103103630798288f   // 384^-0.5
#define STG_T   18944                 // A 10240 + B 8704  (MN-major B)
#define STG_BIG 30720                 // A 10240 (128x80B) + B 20480 (256x80B)
#define SMEM_T3   (3 * STG_T)         // 56832
#define SMEM_BIG3 (3 * STG_BIG)       // 92160
#define SMEM_PV3  (SMEM_T3 + 4096)    // + sg[8 tiles][128 rows] fp32

__device__ __half g_Wh[3 * 384 * 384];           // W[k][n] fp16, Wq pre-scaled
__device__ __half g_Qh[16 * 2048 * 384];
__device__ __half g_Kh[16 * 2048 * 384];
__device__ __half g_Vh[16 * 2048 * 384];
__device__ __half g_Pt[16ll * 2048 * 2048];      // P~ = exp(S - m_tile), fp16
__device__ float  g_mt[16 * 16 * 8 * 128];       // [b][qt][kt256][row] tile max
__device__ float  g_lt[16 * 16 * 8 * 128];       // per-tile row sum

__device__ __forceinline__ uint32_t smem_u32(const void* p) {
    uint32_t a;
    asm("{ .reg .u64 t; cvta.to.shared.u64 t, %1; cvt.u32.u64 %0, t; }" : "=r"(a) : "l"(p));
    return a;
}
__device__ __forceinline__ void ldsm4(uint32_t addr, uint32_t* r) {
    asm volatile("ldmatrix.sync.aligned.m8n8.x4.shared.b16 {%0,%1,%2,%3}, [%4];"
        : "=r"(r[0]), "=r"(r[1]), "=r"(r[2]), "=r"(r[3]) : "r"(addr));
}
__device__ __forceinline__ void ldsm4t(uint32_t addr, uint32_t* r) {
    asm volatile("ldmatrix.sync.aligned.m8n8.x4.trans.shared.b16 {%0,%1,%2,%3}, [%4];"
        : "=r"(r[0]), "=r"(r[1]), "=r"(r[2]), "=r"(r[3]) : "r"(addr));
}
__device__ __forceinline__ void mmah(float* c, const uint32_t* a, const uint32_t* b) {
    asm volatile("mma.sync.aligned.m16n8k16.row.col.f32.f16.f16.f32 "
        "{%0,%1,%2,%3}, {%4,%5,%6,%7}, {%8,%9}, {%0,%1,%2,%3};"
        : "+f"(c[0]), "+f"(c[1]), "+f"(c[2]), "+f"(c[3])
        : "r"(a[0]), "r"(a[1]), "r"(a[2]), "r"(a[3]), "r"(b[0]), "r"(b[1]));
}

#define AOFF(wm, lane) ((uint32_t)(((wm) * 32 + ((lane) & 15)) * 80 + ((lane) >> 4) * 16))
#define BOFFT(wn, lane) ((uint32_t)(((((lane) >> 3) & 1) * 8 + ((lane) & 7)) * 272 + \
                                    ((wn) * 64 + (((lane) >> 4) & 1) * 8) * 2))

// MN-major-B 1-pass chunk (proj/pv): A@0, B@10240 (32 rows x 272B), ldsm.trans.
template <bool SCALED>
__device__ __forceinline__ void chunk1t(uint32_t sbase, uint32_t aOff, uint32_t bOff,
                                        float acc[2][8][4],
                                        const __half2* ga, const __half2* gb) {
#pragma unroll
    for (int ks = 0; ks < 2; ks++) {
        uint32_t a[2][4], b[8][2];
#pragma unroll
        for (int mf = 0; mf < 2; mf++) {
            ldsm4(sbase + aOff + mf * 1280 + ks * 32, a[mf]);
            if (SCALED) {
                __half2* ap = reinterpret_cast<__half2*>(a[mf]);
                ap[0] = __hmul2(ap[0], ga[mf]);
                ap[2] = __hmul2(ap[2], ga[mf]);
                ap[1] = __hmul2(ap[1], gb[mf]);
                ap[3] = __hmul2(ap[3], gb[mf]);
            }
        }
#pragma unroll
        for (int n2 = 0; n2 < 4; n2++) {
            uint32_t r[4];
            ldsm4t(sbase + 10240 + bOff + (uint32_t)(ks * 16 * 272 + n2 * 32), r);
            b[n2 * 2][0] = r[0]; b[n2 * 2][1] = r[1];
            b[n2 * 2 + 1][0] = r[2]; b[n2 * 2 + 1][1] = r[3];
        }
#pragma unroll
        for (int mf = 0; mf < 2; mf++)
#pragma unroll
            for (int nf = 0; nf < 8; nf++) mmah(acc[mf][nf], a[mf], b[nf]);
    }
}

struct __align__(8) hpair { __half2 a, b; };
__device__ __forceinline__ hpair to_h(float4 v) {
    hpair r; r.a = __floats2half2_rn(v.x, v.y); r.b = __floats2half2_rn(v.z, v.w); return r;
}

// ---------------- cvtw: W fp32 -> fp16 (SCALE folded into Wq) ----------------
__global__ void cvtw_kernel(const float* __restrict__ Wq, const float* __restrict__ Wk,
                            const float* __restrict__ Wv) {
    int i = (blockIdx.x * 256 + threadIdx.x) * 4;
    int z = i / 147456, r = i - z * 147456;
    const float* W = (z == 0) ? Wq : ((z == 1) ? Wk : Wv);
    float4 v = *(const float4*)(W + r);
    float s = (z == 0) ? SCALE : 1.f;
    v.x *= s; v.y *= s; v.z *= s; v.w *= s;
    *(hpair*)&g_Wh[i] = to_h(v);
}

// ---------------- proj: 128x128, 3-stage pipeline (R11-proven) ----------------
__global__ void __launch_bounds__(256, 2) proj_kernel(const float* __restrict__ X) {
    extern __shared__ char smem[];
    int tid = threadIdx.x, lane = tid & 31, wid = tid >> 5, wm = wid & 3, wn = wid >> 2;
    uint32_t sb = smem_u32(smem);
    int nt = blockIdx.x * 128, mt = blockIdx.y * 128, z = blockIdx.z;
    const float*  gA = X + (size_t)mt * 384;
    const __half* gW = g_Wh + (size_t)z * 147456 + nt;
    float acc[2][8][4];
#pragma unroll
    for (int i = 0; i < 2; i++)
#pragma unroll
        for (int j = 0; j < 8; j++)
#pragma unroll
            for (int q = 0; q < 4; q++) acc[i][j][q] = 0.f;

    float4 va[4]; uint4 wb[2];
    auto ldg = [&](int c) {
#pragma unroll
        for (int i = 0; i < 4; i++) {
            int lin = tid + 256 * i, row = lin >> 3, c4 = (lin & 7) * 4;
            va[i] = *(const float4*)(gA + (size_t)row * 384 + c * 32 + c4);
        }
#pragma unroll
        for (int i = 0; i < 2; i++) {
            int lin = tid + 256 * i, r2 = lin >> 4, c2 = (lin & 15) * 8;
            wb[i] = *(const uint4*)(gW + (size_t)(c * 32 + r2) * 384 + c2);
        }
    };
    auto stg = [&](char* buf) {
#pragma unroll
        for (int i = 0; i < 4; i++) {
            int lin = tid + 256 * i, row = lin >> 3, c4 = (lin & 7) * 4;
            *(hpair*)(buf + row * 80 + c4 * 2) = to_h(va[i]);
        }
#pragma unroll
        for (int i = 0; i < 2; i++) {
            int lin = tid + 256 * i, r2 = lin >> 4, c2 = (lin & 15) * 8;
            *(uint4*)(buf + 10240 + r2 * 272 + c2 * 2) = wb[i];
        }
    };
    uint32_t aOff = AOFF(wm, lane), bOff = BOFFT(wn, lane);
    ldg(0); stg(smem); ldg(1);
    __syncthreads();
    int rs = 0;
    for (int c = 0; c < 12; c++) {
        int ws = (rs == 2) ? 0 : rs + 1;
        if (c + 1 < 12) stg(smem + ws * STG_T);
        if (c + 2 < 12) ldg(c + 2);
        chunk1t<false>(sb + (uint32_t)(rs * STG_T), aOff, bOff, acc, 0, 0);
        __syncthreads();
        rs = ws;
    }

    __half* Yh = (z == 0) ? g_Qh : ((z == 1) ? g_Kh : g_Vh);
#pragma unroll
    for (int mf = 0; mf < 2; mf++)
#pragma unroll
        for (int h = 0; h < 2; h++) {
            int row = mt + wm * 32 + mf * 16 + (lane >> 2) + h * 8;
#pragma unroll
            for (int nf = 0; nf < 8; nf++) {
                int col = nt + wn * 64 + nf * 8 + (lane & 3) * 2;
                *(__half2*)&Yh[(size_t)row * 384 + col] =
                    __floats2half2_rn(acc[mf][nf][h * 2], acc[mf][nf][h * 2 + 1]);
            }
        }
}

// ---------------- qk: 128x256 CTA tile, 64x64 warp tiles, fused local softmax ----------------
__global__ void __launch_bounds__(256, 1) qk_kernel() {
    extern __shared__ char smem[];
    int tid = threadIdx.x, lane = tid & 31, wid = tid >> 5, wm = wid & 1, wn = wid >> 1;
    uint32_t sb = smem_u32(smem);
    int b = blockIdx.y, r_ = blockIdx.x, qt = 0;
    while (r_ >= (qt >> 1) + 1) { r_ -= (qt >> 1) + 1; qt++; }
    int kt = r_;                          // 256-key tile index
    size_t qb = ((size_t)b * 2048 + qt * 128) * 384;
    size_t kb = ((size_t)b * 2048 + kt * 256) * 384;
    float acc[4][8][4];
#pragma unroll
    for (int i = 0; i < 4; i++)
#pragma unroll
        for (int j = 0; j < 8; j++)
#pragma unroll
            for (int q = 0; q < 4; q++) acc[i][j][q] = 0.f;

    uint4 rva[2], rvb[4];
    auto ldg = [&](int c) {
#pragma unroll
        for (int i = 0; i < 2; i++) {
            int lin = tid + 256 * i, rr = lin >> 2, cc = (lin & 3) * 8;
            rva[i] = *(const uint4*)(g_Qh + qb + (size_t)rr * 384 + c * 32 + cc);
        }
#pragma unroll
        for (int i = 0; i < 4; i++) {
            int lin = tid + 256 * i, rr = lin >> 2, cc = (lin & 3) * 8;
            rvb[i] = *(const uint4*)(g_Kh + kb + (size_t)rr * 384 + c * 32 + cc);
        }
    };
    auto stg = [&](char* buf) {
#pragma unroll
        for (int i = 0; i < 2; i++) {
            int lin = tid + 256 * i, rr = lin >> 2, cc = (lin & 3) * 8;
            *(uint4*)(buf + rr * 80 + cc * 2) = rva[i];
        }
#pragma unroll
        for (int i = 0; i < 4; i++) {
            int lin = tid + 256 * i, rr = lin >> 2, cc = (lin & 3) * 8;
            *(uint4*)(buf + 10240 + rr * 80 + cc * 2) = rvb[i];
        }
    };
    uint32_t aOff = (uint32_t)((wm * 64 + (lane & 15)) * 80 + (lane >> 4) * 16);
    uint32_t bOff = (uint32_t)((wn * 64 + ((lane >> 4) & 1) * 8 + (lane & 7)) * 80 +
                               ((lane >> 3) & 1) * 16);
    ldg(0); stg(smem); ldg(1);
    __syncthreads();
    int rs = 0;
    for (int c = 0; c < 12; c++) {
        int ws = (rs == 2) ? 0 : rs + 1;
        if (c + 1 < 12) stg(smem + ws * STG_BIG);
        if (c + 2 < 12) ldg(c + 2);
        uint32_t sbase = sb + (uint32_t)(rs * STG_BIG);
#pragma unroll
        for (int ks = 0; ks < 2; ks++) {
            uint32_t a[4][4], bfr[8][2];
#pragma unroll
            for (int mf = 0; mf < 4; mf++)
                ldsm4(sbase + aOff + mf * 1280 + ks * 32, a[mf]);
#pragma unroll
            for (int n2 = 0; n2 < 4; n2++) {
                uint32_t r[4];
                ldsm4(sbase + 10240 + bOff + n2 * 1280 + ks * 32, r);
                bfr[n2 * 2][0] = r[0]; bfr[n2 * 2][1] = r[1];
                bfr[n2 * 2 + 1][0] = r[2]; bfr[n2 * 2 + 1][1] = r[3];
            }
#pragma unroll
            for (int mf = 0; mf < 4; mf++)
#pragma unroll
                for (int nf = 0; nf < 8; nf++) mmah(acc[mf][nf], a[mf], bfr[nf]);
        }
        __syncthreads();
        rs = ws;
    }

    // ---- fused epilogue: mask, per-256-tile row max/exp/sum, P~ store ----
    float* sR = (float*)smem;            // [4 wn][128 rows]
    float pm[4][2], ps[4][2];
#pragma unroll
    for (int mf = 0; mf < 4; mf++) { pm[mf][0] = pm[mf][1] = -1e30f; }
#pragma unroll
    for (int mf = 0; mf < 4; mf++)
#pragma unroll
        for (int nf = 0; nf < 8; nf++)
#pragma unroll
            for (int q = 0; q < 4; q++) {
                int h = q >> 1;
                int qg = qt * 128 + wm * 64 + mf * 16 + (lane >> 2) + h * 8;
                int kg = kt * 256 + wn * 64 + nf * 8 + (lane & 3) * 2 + (q & 1);
                if (kg > qg) acc[mf][nf][q] = -1e30f;
                pm[mf][h] = fmaxf(pm[mf][h], acc[mf][nf][q]);
            }
#pragma unroll
    for (int mf = 0; mf < 4; mf++)
#pragma unroll
        for (int h = 0; h < 2; h++) {
            pm[mf][h] = fmaxf(pm[mf][h], __shfl_xor_sync(~0u, pm[mf][h], 1));
            pm[mf][h] = fmaxf(pm[mf][h], __shfl_xor_sync(~0u, pm[mf][h], 2));
        }
    int rl[4][2];
#pragma unroll
    for (int mf = 0; mf < 4; mf++)
#pragma unroll
        for (int h = 0; h < 2; h++)
            rl[mf][h] = wm * 64 + mf * 16 + (lane >> 2) + h * 8;
    if ((lane & 3) == 0)
#pragma unroll
        for (int mf = 0; mf < 4; mf++)
#pragma unroll
            for (int h = 0; h < 2; h++) sR[wn * 128 + rl[mf][h]] = pm[mf][h];
    __syncthreads();
    float mrow[4][2];
#pragma unroll
    for (int mf = 0; mf < 4; mf++)
#pragma unroll
        for (int h = 0; h < 2; h++) {
            mrow[mf][h] = fmaxf(fmaxf(sR[rl[mf][h]], sR[128 + rl[mf][h]]),
                                fmaxf(sR[256 + rl[mf][h]], sR[384 + rl[mf][h]]));
            ps[mf][h] = 0.f;
        }
#pragma unroll
    for (int mf = 0; mf < 4; mf++)
#pragma unroll
        for (int nf = 0; nf < 8; nf++)
#pragma unroll
            for (int q = 0; q < 4; q++) {
                int h = q >> 1;
                float p = __expf(acc[mf][nf][q] - mrow[mf][h]);
                acc[mf][nf][q] = p;
                ps[mf][h] += p;
            }
#pragma unroll
    for (int mf = 0; mf < 4; mf++)
#pragma unroll
        for (int h = 0; h < 2; h++) {
            ps[mf][h] += __shfl_xor_sync(~0u, ps[mf][h], 1);
            ps[mf][h] += __shfl_xor_sync(~0u, ps[mf][h], 2);
        }
    __syncthreads();
    if ((lane & 3) == 0)
#pragma unroll
        for (int mf = 0; mf < 4; mf++)
#pragma unroll
            for (int h = 0; h < 2; h++) sR[wn * 128 + rl[mf][h]] = ps[mf][h];
    __syncthreads();
    size_t statb = ((size_t)(b * 16 + qt) * 8 + kt) * 128;
    if (wn == 0 && (lane & 3) == 0)
#pragma unroll
        for (int mf = 0; mf < 4; mf++)
#pragma unroll
            for (int h = 0; h < 2; h++) {
                g_mt[statb + rl[mf][h]] = mrow[mf][h];
                g_lt[statb + rl[mf][h]] = sR[rl[mf][h]] + sR[128 + rl[mf][h]] +
                                          sR[256 + rl[mf][h]] + sR[384 + rl[mf][h]];
            }
    __half* Prow = g_Pt + ((size_t)b * 2048 + qt * 128) * 2048 + (size_t)kt * 256;
#pragma unroll
    for (int mf = 0; mf < 4; mf++)
#pragma unroll
        for (int h = 0; h < 2; h++) {
#pragma unroll
            for (int nf = 0; nf < 8; nf++) {
                int col = wn * 64 + nf * 8 + (lane & 3) * 2;
                *(__half2*)&Prow[(size_t)rl[mf][h] * 2048 + col] =
                    __floats2half2_rn(acc[mf][nf][h * 2], acc[mf][nf][h * 2 + 1]);
            }
        }
}

// ---------------- pv: 3-stage pipeline; fused norm (<=8 tiles); g on A fragments ----------------
__global__ void __launch_bounds__(256, 2) pv_kernel(float* __restrict__ out) {
    extern __shared__ char smem[];
    int tid = threadIdx.x, lane = tid & 31, wid = tid >> 5, wm = wid & 3, wn = wid >> 2;
    uint32_t sb = smem_u32(smem);
    int nt = blockIdx.x * 128, qt = 15 - (int)blockIdx.y, b = blockIdx.z;
    int nch = (qt + 1) * 4;              // 32-key chunks
    const __half* Pb = g_Pt + ((size_t)b * 2048 + qt * 128) * 2048;
    const __half* Vh = g_Vh + (size_t)b * 2048 * 384 + nt;
    float* sg = (float*)(smem + SMEM_T3);        // [8 tiles][128 rows]
    float acc[2][8][4];
#pragma unroll
    for (int i = 0; i < 2; i++)
#pragma unroll
        for (int j = 0; j < 8; j++)
#pragma unroll
            for (int q = 0; q < 4; q++) acc[i][j][q] = 0.f;

    uint4 rv[4];
    auto ldg = [&](int c) {
#pragma unroll
        for (int i = 0; i < 2; i++) {
            int lin = tid + 256 * i;
            int rr = lin >> 2, cc = (lin & 3) * 8;            // A: 128 x 32
            rv[i * 2 + 0] = *(const uint4*)(Pb + (size_t)rr * 2048 + c * 32 + cc);
            int r2 = lin >> 4, c2 = (lin & 15) * 8;           // B: 32 x 128
            rv[i * 2 + 1] = *(const uint4*)(Vh + (size_t)(c * 32 + r2) * 384 + c2);
        }
    };
    auto stg = [&](char* buf) {
#pragma unroll
        for (int i = 0; i < 2; i++) {
            int lin = tid + 256 * i;
            int rr = lin >> 2, cc = (lin & 3) * 8;
            *(uint4*)(buf + rr * 80 + cc * 2) = rv[i * 2 + 0];
            int r2 = lin >> 4, c2 = (lin & 15) * 8;
            *(uint4*)(buf + 10240 + r2 * 272 + c2 * 2) = rv[i * 2 + 1];
        }
    };
    uint32_t aOff = AOFF(wm, lane), bOff = BOFFT(wn, lane);
    ldg(0);
    // fused norm: per-row fold factors over <=8 stat tiles (overlaps ldg latency)
    if (tid < 128) {
        int ntl = (qt >> 1) + 1;
        size_t base = ((size_t)(b * 16 + qt) * 8) * 128 + tid;
        float m = -1e30f;
        for (int t = 0; t < ntl; t++) m = fmaxf(m, g_mt[base + t * 128]);
        float l = 0.f;
        for (int t = 0; t < ntl; t++) l += __expf(g_mt[base + t * 128] - m) * g_lt[base + t * 128];
        float inv = 1.f / l;
        for (int t = 0; t < ntl; t++)
            sg[t * 128 + tid] = __expf(g_mt[base + t * 128] - m) * inv;
    }
    stg(smem); ldg(1);
    __syncthreads();

    int rbase = wm * 32 + (lane >> 2);
    int rs = 0;
    __half2 ga[2], gb[2];
    for (int c = 0; c < nch; c++) {
        if ((c & 7) == 0) {
            const float* gp = sg + (c >> 3) * 128;
#pragma unroll
            for (int mf = 0; mf < 2; mf++) {
                ga[mf] = __float2half2_rn(gp[rbase + mf * 16]);
                gb[mf] = __float2half2_rn(gp[rbase + mf * 16 + 8]);
            }
        }
        int ws = (rs == 2) ? 0 : rs + 1;
        if (c + 1 < nch) stg(smem + ws * STG_T);
        if (c + 2 < nch) ldg(c + 2);
        chunk1t<true>(sb + (uint32_t)(rs * STG_T), aOff, bOff, acc, ga, gb);
        __syncthreads();
        rs = ws;
    }

    float* Y = out + ((size_t)b * 2048 + qt * 128) * 384 + nt;
#pragma unroll
    for (int mf = 0; mf < 2; mf++)
#pragma unroll
        for (int h = 0; h < 2; h++) {
            int row = wm * 32 + mf * 16 + (lane >> 2) + h * 8;
#pragma unroll
            for (int nf = 0; nf < 8; nf++) {
                float2 v = make_float2(acc[mf][nf][h * 2], acc[mf][nf][h * 2 + 1]);
                *(float2*)&Y[(size_t)row * 384 + wn * 64 + nf * 8 + (lane & 3) * 2] = v;
            }
        }
}

extern "C" void kernel_launch(void* const* d_in, const int* in_sizes, int n_in,
                              void* d_out, int out_size) {
    const float* x  = (const float*)d_in[0];
    const float* Wq = (const float*)d_in[1];
    const float* Wk = (const float*)d_in[2];
    const float* Wv = (const float*)d_in[3];
    float* out = (float*)d_out;
    (void)in_sizes; (void)n_in; (void)out_size;

    cudaFuncSetAttribute(proj_kernel, cudaFuncAttributeMaxDynamicSharedMemorySize, SMEM_T3);
    cudaFuncSetAttribute(qk_kernel,   cudaFuncAttributeMaxDynamicSharedMemorySize, SMEM_BIG3);
    cudaFuncSetAttribute(pv_kernel,   cudaFuncAttributeMaxDynamicSharedMemorySize, SMEM_PV3);

    cvtw_kernel<<<432, 256>>>(Wq, Wk, Wv);
    proj_kernel<<<dim3(3, 256, 3), 256, SMEM_T3>>>(x);
    qk_kernel<<<dim3(72, 16), 256, SMEM_BIG3>>>();   // sum over qt of (qt/2+1) = 72
    pv_kernel<<<dim3(3, 16, 16), 256, SMEM_PV3>>>(out);
}